// round 1
// baseline (speedup 1.0000x reference)
#include <cuda_runtime.h>
#include <math.h>

// ---------------- problem constants ----------------
#define BATCH 2
#define CH    256
#define NH    4
#define DK    64          // CH / NH
#define HW_N  2304        // 48*48
#define C2    512         // 2*CH

// ---------------- scratch (device globals; no allocation allowed) ----------
__device__ float g_xs[BATCH*CH*HW_N];
__device__ float g_ys[BATCH*CH*HW_N];
__device__ float g_q [BATCH*CH*HW_N];
__device__ float g_k [BATCH*CH*HW_N];
__device__ float g_v [BATCH*CH*HW_N];
__device__ float g_x2[BATCH*CH*HW_N];
__device__ float g_y2[BATCH*CH*HW_N];
__device__ float g_S [(size_t)BATCH*NH*HW_N*HW_N];   // 170 MB attention scratch
__device__ float g_pooled[BATCH*C2];
__device__ float g_sescale[BATCH*C2];                // 1 + sigmoid(f)
__device__ float g_gate[BATCH*2*HW_N];               // 1 + sigmoid(gate)

__device__ __forceinline__ float sigmoidf_(float v){ return 1.f/(1.f+expf(-v)); }

// ---------------- 1. channel-mean pooling ----------------
__global__ void pool_kernel(const float* __restrict__ x, const float* __restrict__ y)
{
    int idx = blockIdx.x;                 // over BATCH*2C
    int b = idx / C2, ch = idx % C2;
    const float* src = (ch < CH) ? (x + ((long)b*CH + ch)*HW_N)
                                 : (y + ((long)b*CH + (ch-CH))*HW_N);
    float s = 0.f;
    for (int i = threadIdx.x; i < HW_N; i += 256) s += src[i];
    __shared__ float red[256];
    red[threadIdx.x] = s; __syncthreads();
    for (int st = 128; st > 0; st >>= 1) {
        if (threadIdx.x < st) red[threadIdx.x] += red[threadIdx.x+st];
        __syncthreads();
    }
    if (threadIdx.x == 0) g_pooled[idx] = red[0] / (float)HW_N;
}

// ---------------- 2. SE MLP (tiny) ----------------
__global__ void se_kernel(const float* __restrict__ w1, const float* __restrict__ b1,
                          const float* __restrict__ w2, const float* __restrict__ b2)
{
    int b = blockIdx.x, t = threadIdx.x;   // block of 512
    __shared__ float sp[C2], sh[DK];
    sp[t] = g_pooled[b*C2 + t];
    __syncthreads();
    if (t < DK) {
        float s = b1[t];
        for (int c = 0; c < C2; c++) s += w1[t*C2 + c] * sp[c];
        sh[t] = fmaxf(s, 0.f);
    }
    __syncthreads();
    float f = b2[t];
    for (int j = 0; j < DK; j++) f += w2[t*DK + j] * sh[j];
    g_sescale[b*C2 + t] = 1.f + sigmoidf_(f);
}

// ---------------- 3. elementwise SE scale ----------------
__global__ void scale_kernel(const float* __restrict__ x, const float* __restrict__ y)
{
    long i = (long)blockIdx.x*blockDim.x + threadIdx.x;
    if (i >= (long)BATCH*CH*HW_N) return;
    int b = (int)(i / (CH*HW_N));
    int c = (int)((i / HW_N) % CH);
    g_xs[i] = x[i] * g_sescale[b*C2 + c];
    g_ys[i] = y[i] * g_sescale[b*C2 + CH + c];
}

// ---------------- 4. generic batched fp32 GEMM: C = A*B (+bias) ----------------
// !TRANS_A: A[m,k] at A[m*lda+k];  TRANS_A: A[m,k] at A[k*lda+m]
#define BM 64
#define BN 64
#define BK 16

template<bool TRANS_A, bool HAS_BIAS>
__global__ void __launch_bounds__(256)
gemm_kernel(const float* __restrict__ A, const float* __restrict__ Bm,
            float* __restrict__ Cm, const float* __restrict__ bias,
            int M, int Nn, int K, int lda, int ldb, int ldc,
            long long sA, long long sB, long long sC)
{
    __shared__ float As[BK][BM+4];
    __shared__ float Bs[BK][BN+4];
    int z = blockIdx.z;
    A  += sA * z;  Bm += sB * z;  Cm += sC * z;
    int bm = blockIdx.y * BM, bn = blockIdx.x * BN;
    int t  = threadIdx.x;
    int tx = t & 15, ty = t >> 4;
    float acc[4][4] = {};
    for (int k0 = 0; k0 < K; k0 += BK) {
        if (TRANS_A) {
            int lm = t & 63, lk = t >> 6;
            #pragma unroll
            for (int i = 0; i < 4; i++)
                As[lk + 4*i][lm] = A[(long)(k0 + lk + 4*i)*lda + bm + lm];
        } else {
            int lc = t & 15, lr = t >> 4;
            #pragma unroll
            for (int i = 0; i < 4; i++)
                As[lc][lr + 16*i] = A[(long)(bm + lr + 16*i)*lda + k0 + lc];
        }
        {
            int ln = t & 63, lk = t >> 6;
            #pragma unroll
            for (int i = 0; i < 4; i++)
                Bs[lk + 4*i][ln] = Bm[(long)(k0 + lk + 4*i)*ldb + bn + ln];
        }
        __syncthreads();
        #pragma unroll
        for (int k = 0; k < BK; k++) {
            float4 av = *reinterpret_cast<const float4*>(&As[k][ty*4]);
            float4 bv = *reinterpret_cast<const float4*>(&Bs[k][tx*4]);
            float a[4] = {av.x, av.y, av.z, av.w};
            float b[4] = {bv.x, bv.y, bv.z, bv.w};
            #pragma unroll
            for (int i = 0; i < 4; i++)
                #pragma unroll
                for (int j = 0; j < 4; j++)
                    acc[i][j] += a[i]*b[j];
        }
        __syncthreads();
    }
    #pragma unroll
    for (int i = 0; i < 4; i++) {
        float bvv = HAS_BIAS ? bias[bm + ty*4 + i] : 0.f;
        #pragma unroll
        for (int j = 0; j < 4; j++)
            Cm[(long)(bm + ty*4 + i)*ldc + bn + tx*4 + j] = acc[i][j] + bvv;
    }
}

// ---------------- 5. row softmax (scale 1/8 folded into exp) ----------------
__global__ void softmax_kernel(float* __restrict__ S)
{
    long row = blockIdx.x;
    float* p = S + row * (long)HW_N;
    __shared__ float buf[HW_N];
    __shared__ float red[256];
    int t = threadIdx.x;
    float mx = -1e30f;
    for (int i = t; i < HW_N; i += 256) { float v = p[i]; buf[i] = v; mx = fmaxf(mx, v); }
    red[t] = mx; __syncthreads();
    for (int st = 128; st > 0; st >>= 1) {
        if (t < st) red[t] = fmaxf(red[t], red[t+st]);
        __syncthreads();
    }
    mx = red[0];
    __syncthreads();
    float sm = 0.f;
    for (int i = t; i < HW_N; i += 256) {
        float e = __expf((buf[i] - mx) * 0.125f);
        buf[i] = e; sm += e;
    }
    red[t] = sm; __syncthreads();
    for (int st = 128; st > 0; st >>= 1) {
        if (t < st) red[t] += red[t+st];
        __syncthreads();
    }
    float inv = 1.f / red[0];
    for (int i = t; i < HW_N; i += 256) p[i] = buf[i] * inv;
}

// ---------------- 6. gating dot products ----------------
__global__ void gate_kernel(const float* __restrict__ gw, const float* __restrict__ gb)
{
    int i = blockIdx.x*blockDim.x + threadIdx.x;   // over BATCH*HW_N
    if (i >= BATCH*HW_N) return;
    int b = i / HW_N, m = i % HW_N;
    const float* xb = g_x2 + (long)b*CH*HW_N + m;
    const float* yb = g_y2 + (long)b*CH*HW_N + m;
    float s0 = gb[0], s1 = gb[1];
    for (int c = 0; c < CH; c++) {
        float xv = xb[(long)c*HW_N];
        s0 += gw[c]        * xv;
        s1 += gw[C2 + c]   * xv;
    }
    for (int c = 0; c < CH; c++) {
        float yv = yb[(long)c*HW_N];
        s0 += gw[CH + c]       * yv;
        s1 += gw[C2 + CH + c]  * yv;
    }
    g_gate[b*2*HW_N + m]        = 1.f + sigmoidf_(s0);
    g_gate[b*2*HW_N + HW_N + m] = 1.f + sigmoidf_(s1);
}

// ---------------- 7. final gated writeback ----------------
__global__ void final_kernel(float* __restrict__ out)
{
    long i = (long)blockIdx.x*blockDim.x + threadIdx.x;
    if (i >= (long)BATCH*CH*HW_N) return;
    int b = (int)(i / (CH*HW_N));
    int m = (int)(i % HW_N);
    out[i]                       = g_x2[i] * g_gate[b*2*HW_N + m];
    out[(long)BATCH*CH*HW_N + i] = g_y2[i] * g_gate[b*2*HW_N + HW_N + m];
}

// ---------------- host orchestration ----------------
extern "C" void kernel_launch(void* const* d_in, const int* in_sizes, int n_in,
                              void* d_out, int out_size)
{
    const float* x      = (const float*)d_in[0];
    const float* y      = (const float*)d_in[1];
    const float* fc1w   = (const float*)d_in[2];
    const float* fc1b   = (const float*)d_in[3];
    const float* fc2w   = (const float*)d_in[4];
    const float* fc2b   = (const float*)d_in[5];
    const float* t1_qw  = (const float*)d_in[6];
    const float* t1_qb  = (const float*)d_in[7];
    const float* t1_kw  = (const float*)d_in[8];
    const float* t1_kb  = (const float*)d_in[9];
    const float* t1_vw  = (const float*)d_in[10];
    const float* t1_vb  = (const float*)d_in[11];
    const float* t2_qw  = (const float*)d_in[12];
    const float* t2_qb  = (const float*)d_in[13];
    const float* t2_kw  = (const float*)d_in[14];
    const float* t2_kb  = (const float*)d_in[15];
    const float* t2_vw  = (const float*)d_in[16];
    const float* t2_vb  = (const float*)d_in[17];
    const float* gate_w = (const float*)d_in[18];
    const float* gate_b = (const float*)d_in[19];

    float *xs, *ys, *q, *k, *v, *S, *x2, *y2;
    cudaGetSymbolAddress((void**)&xs, g_xs);
    cudaGetSymbolAddress((void**)&ys, g_ys);
    cudaGetSymbolAddress((void**)&q,  g_q);
    cudaGetSymbolAddress((void**)&k,  g_k);
    cudaGetSymbolAddress((void**)&v,  g_v);
    cudaGetSymbolAddress((void**)&S,  g_S);
    cudaGetSymbolAddress((void**)&x2, g_x2);
    cudaGetSymbolAddress((void**)&y2, g_y2);

    const long total = (long)BATCH*CH*HW_N;

    // --- RScaling ---
    pool_kernel<<<BATCH*C2, 256>>>(x, y);
    se_kernel<<<BATCH, C2>>>(fc1w, fc1b, fc2w, fc2b);
    scale_kernel<<<(int)((total + 255)/256), 256>>>(x, y);

    // conv1x1: out[b, o, p] = sum_c w[o,c]*in[b,c,p] + bias[o]
    auto conv = [&](const float* w, const float* src, float* dst, const float* bias) {
        gemm_kernel<false, true><<<dim3(HW_N/BN, CH/BM, BATCH), 256>>>(
            w, src, dst, bias,
            CH, HW_N, CH, CH, HW_N, HW_N,
            0LL, (long long)CH*HW_N, (long long)CH*HW_N);
    };

    auto rtrans = [&](const float* qin, const float* kvin,
                      const float* qw, const float* qb,
                      const float* kw, const float* kb,
                      const float* vw, const float* vb, float* outp) {
        conv(qw, qin,  q, qb);
        conv(kw, kvin, k, kb);
        conv(vw, kvin, v, vb);
        // scores[n,m] = sum_d q[d,n]*k[d,m]  (q transposed access)
        gemm_kernel<true, false><<<dim3(HW_N/BN, HW_N/BM, BATCH*NH), 256>>>(
            q, k, S, nullptr,
            HW_N, HW_N, DK, HW_N, HW_N, HW_N,
            (long long)DK*HW_N, (long long)DK*HW_N, (long long)HW_N*HW_N);
        softmax_kernel<<<BATCH*NH*HW_N, 256>>>(S);
        // out[d,m] = sum_n v[d,n]*attn[n,m]
        gemm_kernel<false, false><<<dim3(HW_N/BN, DK/BM, BATCH*NH), 256>>>(
            v, S, outp, nullptr,
            DK, HW_N, HW_N, HW_N, HW_N, HW_N,
            (long long)DK*HW_N, (long long)HW_N*HW_N, (long long)DK*HW_N);
    };

    // RTrans 1: x = attn(q=xs, k=ys, v=ys)
    rtrans(xs, ys, t1_qw, t1_qb, t1_kw, t1_kb, t1_vw, t1_vb, x2);
    // RTrans 2: y = attn(q=ys, k=x2, v=x2)
    rtrans(ys, x2, t2_qw, t2_qb, t2_kw, t2_kb, t2_vw, t2_vb, y2);

    // --- RGating + final writeback ---
    gate_kernel<<<(BATCH*HW_N + 255)/256, 256>>>(gate_w, gate_b);
    final_kernel<<<(int)((total + 255)/256), 256>>>((float*)d_out);
}